// round 1
// baseline (speedup 1.0000x reference)
#include <cuda_runtime.h>

// Problem constants (from reference):
//   VOCAB=128, EMB=256, NUM_CHARS=257, BATCH=8, Lm1=256
#define BATCH_N   8
#define LM1       256
#define EMB_N     256
#define ROWS      257   // output rows per batch (start row + 256)

// Precomputed scan results (scratch; no allocation allowed).
// g_prefix[c] = sum_{w=1}^{c-1} dense_w[w]
// g_tail[c]   = sum_{w=c+2}^{255} dense_w[w]   (for the relu(bias) tail; bias==0 here)
__device__ float g_prefix[LM1];
__device__ float g_tail[LM1];

__global__ void scan_kernel(const float* __restrict__ dense_w) {
    __shared__ float s[LM1];
    int t = threadIdx.x;
    s[t] = dense_w[t];
    __syncthreads();
    // Hillis-Steele inclusive scan: s[t] = sum_{0..t} dense_w
    #pragma unroll
    for (int off = 1; off < LM1; off <<= 1) {
        float v = (t >= off) ? s[t - off] : 0.f;
        __syncthreads();
        s[t] += v;
        __syncthreads();
    }
    float total = s[LM1 - 1];
    float dw0 = dense_w[0];
    // P[0]=0 ; P[c] = S[c-1] - dw[0] for c>=1
    g_prefix[t] = (t == 0) ? 0.f : (s[t - 1] - dw0);
    // T[c] = total - S[c+1] for c<=254 ; T[255]=0
    g_tail[t] = (t >= LM1 - 1) ? 0.f : (total - s[t + 1]);
}

__global__ void __launch_bounds__(EMB_N)
encoder_kernel(const int*   __restrict__ tokens,     // (8, 257) int32
               const float* __restrict__ emb,        // (128, 256)
               const float* __restrict__ dw_kernel,  // (256, 1, 3, 3)
               const float* __restrict__ dw_bias,    // (256,)
               const float* __restrict__ dense_w,    // (256, 1)
               const float* __restrict__ dense_b,    // (1,)
               const float* __restrict__ start_var,  // (1, 256)
               float*       __restrict__ out)        // (8, 257, 256)
{
    const int r = blockIdx.x % ROWS;      // output row within batch
    const int b = blockIdx.x / ROWS;
    const int e = threadIdx.x;
    float* orow = out + ((size_t)b * ROWS + r) * EMB_N;

    if (r == 0) {
        orow[e] = start_var[e];
        return;
    }
    const int c = r - 1;

    __shared__ float sx[EMB_N];
    const int tok = tokens[b * (LM1 + 1) + c];   // tokens[:, :-1][b, c]
    sx[e] = emb[tok * EMB_N + e];
    __syncthreads();

    const float xm = (e > 0)         ? sx[e - 1] : 0.f;   // SAME padding in E
    const float x0 = sx[e];
    const float xp = (e < EMB_N - 1) ? sx[e + 1] : 0.f;

    // dw_kernel[c,0,i,j], row-major 3x3: k[i*3+j]
    const float* k = dw_kernel + c * 9;
    // a_{j'}: cross-correlation taps along E for each W-offset column j' = j-1
    const float A  = fmaf(k[0], xm, fmaf(k[3], x0, k[6] * xp));  // j'=-1 column (j=0)
    const float B  = fmaf(k[1], xm, fmaf(k[4], x0, k[7] * xp));  // j'= 0 column (j=1)
    const float C  = fmaf(k[2], xm, fmaf(k[5], x0, k[8] * xp));  // j'=+1 column (j=2)

    const float bias = dw_bias[c];
    const float r_mid = fmaxf(A + B + C + bias, 0.f);            // 1 <= w <= c-1
    const float r_wc  = fmaxf(A + B + bias, 0.f);                // w == c   (c>=1)
    const float r_wc1 = fmaxf(A + bias, 0.f);                    // w == c+1
    const float r_b   = fmaxf(bias, 0.f);                        // w > c+1 (y==0)

    float acc;
    if (c == 0) {
        // w=0 -> B only ; w=1 -> A ; w>=2 -> bias tail
        acc = dense_w[0] * fmaxf(B + bias, 0.f)
            + dense_w[1] * r_wc1
            + r_b * g_tail[0];
    } else {
        const float r_w0 = fmaxf(B + C + bias, 0.f);             // w == 0 (c>=1)
        acc = dense_w[0] * r_w0
            + g_prefix[c] * r_mid
            + dense_w[c] * r_wc
            + r_b * g_tail[c];
        if (c + 1 < LM1) acc = fmaf(dense_w[c + 1], r_wc1, acc);
    }
    orow[e] = fmaxf(acc + dense_b[0], 0.f);
}

extern "C" void kernel_launch(void* const* d_in, const int* in_sizes, int n_in,
                              void* d_out, int out_size) {
    const int*   tokens    = (const int*)  d_in[0];
    const float* emb       = (const float*)d_in[1];
    const float* dw_kernel = (const float*)d_in[2];
    const float* dw_bias   = (const float*)d_in[3];
    const float* dense_w   = (const float*)d_in[4];
    const float* dense_b   = (const float*)d_in[5];
    const float* start_var = (const float*)d_in[6];
    float* out = (float*)d_out;

    scan_kernel<<<1, LM1>>>(dense_w);
    encoder_kernel<<<BATCH_N * ROWS, EMB_N>>>(tokens, emb, dw_kernel, dw_bias,
                                              dense_w, dense_b, start_var, out);
}

// round 2
// speedup vs baseline: 1.5594x; 1.5594x over previous
#include <cuda_runtime.h>

// Problem constants: VOCAB=128, EMB=256, NUM_CHARS=257, BATCH=8, Lm1=256
#define LM1          256
#define EMB_N        256
#define ROWS         257            // output rows per batch (start + 256)
#define BATCH_N      8
#define ROWS_PER_BLK 4
#define THREADS      (64 * ROWS_PER_BLK)
#define TOTAL_ROWS   (BATCH_N * ROWS)   // 2056 = 4 * 514 exactly

__global__ void __launch_bounds__(THREADS)
encoder_fused(const int*   __restrict__ tokens,     // (8, 257) int32
              const float* __restrict__ emb,        // (128, 256)
              const float* __restrict__ dwk,        // (256, 1, 3, 3)
              const float* __restrict__ dwb,        // (256,)
              const float* __restrict__ dw,         // (256, 1)
              const float* __restrict__ db,         // (1,)
              const float* __restrict__ sv,         // (1, 256)
              float*       __restrict__ out)        // (8, 257, 256)
{
    const int tid       = threadIdx.x;
    const int rowInBlk  = tid >> 6;          // 0..3
    const int t         = tid & 63;          // 0..63, handles e = 4t..4t+3
    const int warpInRow = (tid >> 5) & 1;    // 0..1
    const int lane      = tid & 31;

    const int l = blockIdx.x * ROWS_PER_BLK + rowInBlk;   // < 2056 always
    const int b = l / ROWS;
    const int r = l - b * ROWS;
    const int c = r - 1;                     // valid when r > 0
    const bool isStart = (r == 0);

    // ---- masked reduction of dense_w for P[c] = sum_{1..c-1}, T[c] = sum_{c+2..255}
    const float4 dwv = reinterpret_cast<const float4*>(dw)[t];
    float p = 0.f, tl = 0.f;
    if (!isStart) {
        const float vals[4] = {dwv.x, dwv.y, dwv.z, dwv.w};
        #pragma unroll
        for (int j = 0; j < 4; j++) {
            const int w = 4 * t + j;
            if (w >= 1 && w <= c - 1) p  += vals[j];
            if (w >= c + 2)           tl += vals[j];
        }
    }
    #pragma unroll
    for (int off = 16; off; off >>= 1) {
        p  += __shfl_down_sync(0xffffffffu, p,  off);
        tl += __shfl_down_sync(0xffffffffu, tl, off);
    }
    __shared__ float2 s_part[ROWS_PER_BLK][2];
    if (lane == 0) s_part[rowInBlk][warpInRow] = make_float2(p, tl);

    // ---- issue all long-latency loads before the barrier
    float4 x  = make_float4(0.f, 0.f, 0.f, 0.f);
    float  xm = 0.f, xp = 0.f;
    float  k[9];
    float  bias = 0.f, dw0_ = 0.f, dwc = 0.f, dwc1 = 0.f;
    const float db0 = db[0];
    if (!isStart) {
        const int tok = tokens[b * ROWS + c];        // tokens[:, :-1][b, c]
        const float* xrow = emb + tok * EMB_N;
        x = reinterpret_cast<const float4*>(xrow)[t];
        if (t > 0)  xm = xrow[4 * t - 1];
        if (t < 63) xp = xrow[4 * t + 4];
        #pragma unroll
        for (int i = 0; i < 9; i++) k[i] = dwk[c * 9 + i];
        bias = dwb[c];
        dw0_ = dw[0];
        dwc  = dw[c];
        dwc1 = (c + 1 < LM1) ? dw[c + 1] : 0.f;
    }

    __syncthreads();
    const float2 pa = s_part[rowInBlk][0];
    const float2 pb = s_part[rowInBlk][1];
    const float  P  = pa.x + pb.x;
    const float  T  = pa.y + pb.y;

    float4 outv;
    if (isStart) {
        outv = reinterpret_cast<const float4*>(sv)[t];
    } else {
        const float xs[6] = {xm, x.x, x.y, x.z, x.w, xp};
        const float rb = fmaxf(bias, 0.f);
        float res[4];
        #pragma unroll
        for (int j = 0; j < 4; j++) {
            const float a0 = xs[j], a1 = xs[j + 1], a2 = xs[j + 2];
            // conv columns: A = w-offset -1 taps (k[0],k[3],k[6]); B = 0; C = +1
            const float A = fmaf(k[0], a0, fmaf(k[3], a1, k[6] * a2));
            const float B = fmaf(k[1], a0, fmaf(k[4], a1, k[7] * a2));
            const float C = fmaf(k[2], a0, fmaf(k[5], a1, k[8] * a2));
            const float r_wc1 = fmaxf(A + bias, 0.f);        // w == c+1
            float acc;
            if (c == 0) {
                // w=0 -> B ; w=1 -> A ; w>=2 -> bias tail
                acc = dw0_ * fmaxf(B + bias, 0.f) + dwc1 * r_wc1 + rb * T;
            } else {
                const float r_w0  = fmaxf(B + C + bias, 0.f);      // w == 0
                const float r_mid = fmaxf(A + B + C + bias, 0.f);  // 1..c-1
                const float r_wc  = fmaxf(A + B + bias, 0.f);      // w == c
                acc = dw0_ * r_w0 + P * r_mid + dwc * r_wc + dwc1 * r_wc1 + rb * T;
            }
            res[j] = fmaxf(acc + db0, 0.f);
        }
        outv = make_float4(res[0], res[1], res[2], res[3]);
    }
    reinterpret_cast<float4*>(out + (size_t)l * EMB_N)[t] = outv;
}

extern "C" void kernel_launch(void* const* d_in, const int* in_sizes, int n_in,
                              void* d_out, int out_size) {
    const int*   tokens    = (const int*)  d_in[0];
    const float* emb       = (const float*)d_in[1];
    const float* dw_kernel = (const float*)d_in[2];
    const float* dw_bias   = (const float*)d_in[3];
    const float* dense_w   = (const float*)d_in[4];
    const float* dense_b   = (const float*)d_in[5];
    const float* start_var = (const float*)d_in[6];
    float* out = (float*)d_out;

    encoder_fused<<<TOTAL_ROWS / ROWS_PER_BLK, THREADS>>>(
        tokens, emb, dw_kernel, dw_bias, dense_w, dense_b, start_var, out);
}